// round 2
// baseline (speedup 1.0000x reference)
#include <cuda_runtime.h>
#include <math.h>
#include <stdint.h>

#define NN 50000
#define RR 6
#define EE 32768
#define HH 256
#define FF 16
#define NHH 8
#define HDD 32

// ---------------- scratch (device globals; no allocation) ----------------
__device__ float    g_qe  [(size_t)RR*EE*HH];
__device__ float    g_kb  [(size_t)RR*EE*HH];
__device__ float    g_vb  [(size_t)RR*EE*HH];
__device__ float    g_sc  [(size_t)RR*EE*NHH];
__device__ unsigned g_m   [(size_t)RR*NN*NHH];
__device__ float    g_den [(size_t)RR*NN*NHH];
__device__ float    g_agg [(size_t)RR*NN*HH];
__device__ float    g_rel [(size_t)RR*NN*HH];
__device__ float    g_h1  [(size_t)NN*HH];
__device__ float    g_cat [(size_t)NN*2*HH];
__device__ float    g_paths[(size_t)NN*3*HH];
__device__ float    g_stk [(size_t)NN*3*HH];
__device__ float    g_t   [(size_t)NN*3*(HH/2)];
__device__ float    g_comb[(size_t)NN*HH];

// ---------------- helpers ----------------
__device__ __forceinline__ unsigned encodeF(float f) {
    unsigned u = __float_as_uint(f);
    return (u & 0x80000000u) ? ~u : (u | 0x80000000u);
}
__device__ __forceinline__ float decodeF(unsigned u) {
    return (u & 0x80000000u) ? __uint_as_float(u & 0x7fffffffu)
                             : __uint_as_float(~u);
}
__device__ __forceinline__ float gelu_exact(float v) {
    return 0.5f * v * (1.0f + erff(v * 0.7071067811865475f));
}

// ---------------- zero init ----------------
__global__ void zero_kernel() {
    size_t i = (size_t)blockIdx.x * blockDim.x + threadIdx.x;
    if (i < (size_t)RR * NN * HH) g_agg[i] = 0.0f;
    if (i < (size_t)RR * NN * NHH) { g_m[i] = 0u; g_den[i] = 0.0f; }
}

// ---------------- generic tiled SGEMM ----------------
// C[M,Nn] = act(Aload[M,K] @ B[K,Nn] + bias), batched over blockIdx.z.
// ALOAD: 0 plain (A,lda), 1 relstack (A[(c>>8)*relM + row]*256 + (c&255)),
//        2 gather x rows by gidx, 3 gather x + concat edge_attr (K=272).
// Nn must be a multiple of 128, K a multiple of 8.
#define BM 128
#define BN 128
#define BKK 8
#define TM 8
#define TN 8

template<int ALOAD, int ACT>
__global__ __launch_bounds__(256)
void gemm_kernel(const float* __restrict__ A, long long aBatch, int lda,
                 const int*  __restrict__ gidx, long long gBatch,
                 const float* __restrict__ xPtr,
                 const float* __restrict__ eattr, long long eaBatch,
                 const float* __restrict__ B, long long bBatch, int ldb,
                 const float* __restrict__ bias, long long biasBatch,
                 float* __restrict__ C, long long cBatch, int ldc,
                 int M, int Nn, int K, int relM)
{
    const int z = blockIdx.z;
    const float* Bz   = B + (size_t)z * bBatch;
    const float* bz   = bias + (size_t)z * biasBatch;
    float*       Cz   = C + (size_t)z * cBatch;
    const float* Az   = (ALOAD == 0 || ALOAD == 1) ? (A + (size_t)z * aBatch) : nullptr;
    const int*   gz   = (ALOAD >= 2) ? (gidx + (size_t)z * gBatch) : nullptr;
    const float* eaz  = (ALOAD == 3) ? (eattr + (size_t)z * eaBatch) : nullptr;

    const int row0 = blockIdx.y * BM;
    const int col0 = blockIdx.x * BN;

    __shared__ float As[BKK][BM];
    __shared__ float Bs[BKK][BN];

    const int tid  = threadIdx.x;
    const int aRow = tid >> 1;          // 0..127
    const int aK4  = (tid & 1) * 4;     // 0 or 4
    const int bK   = tid >> 5;          // 0..7
    const int bC4  = (tid & 31) * 4;    // 0..124

    const int rowIdx = row0 + aRow;
    const bool rowOK = rowIdx < M;
    int nodeIdx = 0;
    if (ALOAD >= 2) nodeIdx = rowOK ? gz[rowIdx] : 0;

    const int trow = tid >> 4;
    const int tcol = tid & 15;

    float acc[TM][TN];
#pragma unroll
    for (int i = 0; i < TM; i++)
#pragma unroll
        for (int j = 0; j < TN; j++) acc[i][j] = 0.0f;

    for (int k0 = 0; k0 < K; k0 += BKK) {
        float4 av = make_float4(0.f, 0.f, 0.f, 0.f);
        const int kk = k0 + aK4;
        if (rowOK) {
            if (ALOAD == 0) {
                av = *reinterpret_cast<const float4*>(Az + (size_t)rowIdx * lda + kk);
            } else if (ALOAD == 1) {
                const int rel = kk >> 8, cc = kk & 255;
                av = *reinterpret_cast<const float4*>(
                    Az + ((size_t)rel * relM + rowIdx) * 256 + cc);
            } else if (ALOAD == 2) {
                av = *reinterpret_cast<const float4*>(xPtr + (size_t)nodeIdx * 256 + kk);
            } else {
                if (kk < 256)
                    av = *reinterpret_cast<const float4*>(xPtr + (size_t)nodeIdx * 256 + kk);
                else
                    av = *reinterpret_cast<const float4*>(eaz + (size_t)rowIdx * FF + (kk - 256));
            }
        }
        As[aK4 + 0][aRow] = av.x;
        As[aK4 + 1][aRow] = av.y;
        As[aK4 + 2][aRow] = av.z;
        As[aK4 + 3][aRow] = av.w;

        const float4 bv = *reinterpret_cast<const float4*>(
            Bz + (size_t)(k0 + bK) * ldb + col0 + bC4);
        *reinterpret_cast<float4*>(&Bs[bK][bC4]) = bv;

        __syncthreads();
#pragma unroll
        for (int k2 = 0; k2 < BKK; k2++) {
            float a[TM], b[TN];
            float4 t0 = *reinterpret_cast<const float4*>(&As[k2][trow * TM]);
            float4 t1 = *reinterpret_cast<const float4*>(&As[k2][trow * TM + 4]);
            a[0]=t0.x; a[1]=t0.y; a[2]=t0.z; a[3]=t0.w;
            a[4]=t1.x; a[5]=t1.y; a[6]=t1.z; a[7]=t1.w;
            float4 u0 = *reinterpret_cast<const float4*>(&Bs[k2][tcol * TN]);
            float4 u1 = *reinterpret_cast<const float4*>(&Bs[k2][tcol * TN + 4]);
            b[0]=u0.x; b[1]=u0.y; b[2]=u0.z; b[3]=u0.w;
            b[4]=u1.x; b[5]=u1.y; b[6]=u1.z; b[7]=u1.w;
#pragma unroll
            for (int i = 0; i < TM; i++)
#pragma unroll
                for (int j = 0; j < TN; j++)
                    acc[i][j] = fmaf(a[i], b[j], acc[i][j]);
        }
        __syncthreads();
    }

#pragma unroll
    for (int i = 0; i < TM; i++) {
        const int r = row0 + trow * TM + i;
        if (r >= M) continue;
#pragma unroll
        for (int j = 0; j < TN; j++) {
            const int c = col0 + tcol * TN + j;
            float v = acc[i][j] + bz[c];
            if (ACT == 1) v = gelu_exact(v);
            else if (ACT == 2) v = tanhf(v);
            Cz[(size_t)r * ldc + c] = v;
        }
    }
}

// ---------------- edge pass 1: scores + segment max ----------------
__global__ __launch_bounds__(256)
void scores_kernel(const float* __restrict__ qe, const float* __restrict__ kb,
                   const int* __restrict__ eidx, const float* __restrict__ prior,
                   float* __restrict__ sc, unsigned* __restrict__ mEnc)
{
    const int w    = (blockIdx.x * blockDim.x + threadIdx.x) >> 5;  // global edge
    const int lane = threadIdx.x & 31;
    const int r = w >> 15;
    const int e = w & (EE - 1);
    const int dst = eidx[(size_t)r * 2 * EE + EE + e];
    const float* qrow = qe + (size_t)w * HH;
    const float* krow = kb + (size_t)w * HH;
    float s[NHH];
#pragma unroll
    for (int h = 0; h < NHH; h++) {
        float p = qrow[h * HDD + lane] * krow[h * HDD + lane];
#pragma unroll
        for (int o = 16; o; o >>= 1) p += __shfl_xor_sync(0xffffffffu, p, o);
        s[h] = p;
    }
    if (lane == 0) {
#pragma unroll
        for (int h = 0; h < NHH; h++) {
            const float val = s[h] * 0.17677669529663687f * prior[r * NHH + h];
            sc[(size_t)w * NHH + h] = val;
            atomicMax(&mEnc[((size_t)r * NN + dst) * NHH + h], encodeF(val));
        }
    }
}

// ---------------- edge pass 2: exp + segment sum ----------------
__global__ __launch_bounds__(256)
void ex_kernel(const int* __restrict__ eidx, const unsigned* __restrict__ mEnc,
               float* __restrict__ sc, float* __restrict__ den)
{
    const int id = blockIdx.x * blockDim.x + threadIdx.x;  // < RR*EE*NHH
    const int h = id & (NHH - 1);
    const int e = (id >> 3) & (EE - 1);
    const int r = id >> 18;
    const int dst = eidx[(size_t)r * 2 * EE + EE + e];
    const float m = decodeF(mEnc[((size_t)r * NN + dst) * NHH + h]);
    const float ex = expf(sc[id] - m);
    sc[id] = ex;
    atomicAdd(&den[((size_t)r * NN + dst) * NHH + h], ex);
}

// ---------------- edge pass 3: weighted V scatter ----------------
__global__ __launch_bounds__(256)
void agg_kernel(const float* __restrict__ sc, const float* __restrict__ den,
                const float* __restrict__ vb, const int* __restrict__ eidx,
                float* __restrict__ agg)
{
    const int w    = (blockIdx.x * blockDim.x + threadIdx.x) >> 5;
    const int lane = threadIdx.x & 31;
    const int r = w >> 15;
    const int e = w & (EE - 1);
    const int dst = eidx[(size_t)r * 2 * EE + EE + e];
    const float* vrow = vb + (size_t)w * HH;
    float* arow = agg + ((size_t)r * NN + dst) * HH;
#pragma unroll
    for (int h = 0; h < NHH; h++) {
        const float wt = sc[(size_t)w * NHH + h]
                       / (den[((size_t)r * NN + dst) * NHH + h] + 1e-16f);
        atomicAdd(&arow[h * HDD + lane], wt * vrow[h * HDD + lane]);
    }
}

// ---------------- inter-relation softmax mix + meta paths ----------------
__global__ __launch_bounds__(256)
void inter_kernel(const float* __restrict__ h1, const float* __restrict__ Wir2,
                  const float* __restrict__ bir2, const float* __restrict__ rel,
                  float* __restrict__ cat, float* __restrict__ paths)
{
    const int n = blockIdx.x;
    const int tid = threadIdx.x;
    __shared__ float red[256];
    __shared__ float s_logit[RR];
    __shared__ float wsm[RR];

    const float hv = h1[(size_t)n * HH + tid];
    for (int r = 0; r < RR; r++) {
        red[tid] = hv * Wir2[tid * RR + r];
        __syncthreads();
        for (int s = 128; s > 0; s >>= 1) {
            if (tid < s) red[tid] += red[tid + s];
            __syncthreads();
        }
        if (tid == 0) s_logit[r] = red[0] + bir2[r];
        __syncthreads();
    }
    if (tid == 0) {
        float mx = s_logit[0];
        for (int r = 1; r < RR; r++) mx = fmaxf(mx, s_logit[r]);
        float sum = 0.f;
        float ex[RR];
        for (int r = 0; r < RR; r++) { ex[r] = expf(s_logit[r] - mx); sum += ex[r]; }
        for (int r = 0; r < RR; r++) wsm[r] = ex[r] / sum;
    }
    __syncthreads();

    float v[RR];
#pragma unroll
    for (int r = 0; r < RR; r++) v[r] = rel[((size_t)r * NN + n) * HH + tid];
    float inter = 0.f;
#pragma unroll
    for (int r = 0; r < RR; r++) inter += wsm[r] * v[r];
    cat[(size_t)n * 2 * HH + tid] = inter;
    paths[((size_t)n * 3 + 0) * HH + tid] = v[2] + v[3];
    paths[((size_t)n * 3 + 1) * HH + tid] = v[4] + v[0];
    paths[((size_t)n * 3 + 2) * HH + tid] = v[1] + v[5];
}

// ---------------- meta attention + layernorm ----------------
__global__ __launch_bounds__(256)
void meta_kernel(const float* __restrict__ tb, const float* __restrict__ Wa2,
                 const float* __restrict__ stk, const float* __restrict__ gm,
                 const float* __restrict__ bm, float* __restrict__ cat)
{
    const int n = blockIdx.x;
    const int tid = threadIdx.x;
    __shared__ float red[256];
    __shared__ float s_logit[3];
    __shared__ float attn[3];
    __shared__ float s_mu, s_rstd;

    for (int p = 0; p < 3; p++) {
        float pv = 0.f;
        if (tid < 128) pv = tb[(size_t)n * 384 + p * 128 + tid] * Wa2[tid];
        red[tid] = pv;
        __syncthreads();
        for (int s = 128; s > 0; s >>= 1) {
            if (tid < s) red[tid] += red[tid + s];
            __syncthreads();
        }
        if (tid == 0) s_logit[p] = red[0];
        __syncthreads();
    }
    if (tid == 0) {
        float mx = fmaxf(s_logit[0], fmaxf(s_logit[1], s_logit[2]));
        float e0 = expf(s_logit[0] - mx), e1 = expf(s_logit[1] - mx), e2 = expf(s_logit[2] - mx);
        float sum = e0 + e1 + e2;
        attn[0] = e0 / sum; attn[1] = e1 / sum; attn[2] = e2 / sum;
    }
    __syncthreads();

    float mp = attn[0] * stk[((size_t)n * 3 + 0) * HH + tid]
             + attn[1] * stk[((size_t)n * 3 + 1) * HH + tid]
             + attn[2] * stk[((size_t)n * 3 + 2) * HH + tid];

    red[tid] = mp;
    __syncthreads();
    for (int s = 128; s > 0; s >>= 1) { if (tid < s) red[tid] += red[tid + s]; __syncthreads(); }
    if (tid == 0) s_mu = red[0] / (float)HH;
    __syncthreads();
    const float d = mp - s_mu;
    red[tid] = d * d;
    __syncthreads();
    for (int s = 128; s > 0; s >>= 1) { if (tid < s) red[tid] += red[tid + s]; __syncthreads(); }
    if (tid == 0) s_rstd = rsqrtf(red[0] / (float)HH + 1e-5f);
    __syncthreads();

    cat[(size_t)n * 2 * HH + HH + tid] = d * s_rstd * gm[tid] + bm[tid];
}

// ---------------- final residual + layernorm ----------------
__global__ __launch_bounds__(256)
void out_kernel(const float* __restrict__ x, const float* __restrict__ comb,
                const float* __restrict__ g, const float* __restrict__ b,
                float* __restrict__ out)
{
    const int n = blockIdx.x;
    const int tid = threadIdx.x;
    __shared__ float red[256];
    __shared__ float s_mu, s_rstd;

    const float y = x[(size_t)n * HH + tid] + comb[(size_t)n * HH + tid];
    red[tid] = y;
    __syncthreads();
    for (int s = 128; s > 0; s >>= 1) { if (tid < s) red[tid] += red[tid + s]; __syncthreads(); }
    if (tid == 0) s_mu = red[0] / (float)HH;
    __syncthreads();
    const float d = y - s_mu;
    red[tid] = d * d;
    __syncthreads();
    for (int s = 128; s > 0; s >>= 1) { if (tid < s) red[tid] += red[tid + s]; __syncthreads(); }
    if (tid == 0) s_rstd = rsqrtf(red[0] / (float)HH + 1e-5f);
    __syncthreads();

    out[(size_t)n * HH + tid] = d * s_rstd * g[tid] + b[tid];
}

// ---------------- launch ----------------
extern "C" void kernel_launch(void* const* d_in, const int* in_sizes, int n_in,
                              void* d_out, int out_size)
{
    (void)in_sizes; (void)n_in; (void)out_size;
    const float* x     = (const float*)d_in[0];
    const int*   eidx  = (const int*)  d_in[1];
    const float* eattr = (const float*)d_in[2];
    const float* Wq    = (const float*)d_in[3];
    const float* bq    = (const float*)d_in[4];
    const float* Wk    = (const float*)d_in[5];
    const float* bk    = (const float*)d_in[6];
    const float* Wv    = (const float*)d_in[7];
    const float* bv    = (const float*)d_in[8];
    const float* prior = (const float*)d_in[9];
    const float* Wm    = (const float*)d_in[10];
    const float* bm    = (const float*)d_in[11];
    const float* Wir1  = (const float*)d_in[12];
    const float* bir1  = (const float*)d_in[13];
    const float* Wir2  = (const float*)d_in[14];
    const float* bir2  = (const float*)d_in[15];
    const float* Wmp   = (const float*)d_in[16];
    const float* bmp   = (const float*)d_in[17];
    const float* Wa1   = (const float*)d_in[18];
    const float* ba1   = (const float*)d_in[19];
    const float* Wa2   = (const float*)d_in[20];
    const float* gmeta = (const float*)d_in[21];
    const float* bmeta = (const float*)d_in[22];
    const float* Wc    = (const float*)d_in[23];
    const float* bc    = (const float*)d_in[24];
    const float* gout  = (const float*)d_in[25];
    const float* bout  = (const float*)d_in[26];
    float* out = (float*)d_out;

    float *p_qe, *p_kb, *p_vb, *p_sc, *p_den, *p_agg, *p_rel, *p_h1,
          *p_cat, *p_paths, *p_stk, *p_t, *p_comb;
    unsigned* p_m;
    cudaGetSymbolAddress((void**)&p_qe,   g_qe);
    cudaGetSymbolAddress((void**)&p_kb,   g_kb);
    cudaGetSymbolAddress((void**)&p_vb,   g_vb);
    cudaGetSymbolAddress((void**)&p_sc,   g_sc);
    cudaGetSymbolAddress((void**)&p_m,    g_m);
    cudaGetSymbolAddress((void**)&p_den,  g_den);
    cudaGetSymbolAddress((void**)&p_agg,  g_agg);
    cudaGetSymbolAddress((void**)&p_rel,  g_rel);
    cudaGetSymbolAddress((void**)&p_h1,   g_h1);
    cudaGetSymbolAddress((void**)&p_cat,  g_cat);
    cudaGetSymbolAddress((void**)&p_paths,g_paths);
    cudaGetSymbolAddress((void**)&p_stk,  g_stk);
    cudaGetSymbolAddress((void**)&p_t,    g_t);
    cudaGetSymbolAddress((void**)&p_comb, g_comb);

    const dim3 blk(256);
    const int gridN = (NN + BM - 1) / BM;          // 391
    const int gridE = EE / BM;                     // 256
    const int grid3N = (3 * NN + BM - 1) / BM;     // 1172

    // zero m/den/agg
    zero_kernel<<<(RR * NN * HH + 255) / 256, blk>>>();

    // q = x[dst] @ Wq + bq    [per relation]
    gemm_kernel<2, 0><<<dim3(2, gridE, RR), blk>>>(
        nullptr, 0, 0, eidx + EE, (long long)2 * EE, x, nullptr, 0,
        Wq, 65536, HH, bq, HH, p_qe, (long long)EE * HH, HH, EE, HH, HH, 0);
    // k = [x[src] | eattr] @ Wk + bk
    gemm_kernel<3, 0><<<dim3(2, gridE, RR), blk>>>(
        nullptr, 0, 0, eidx, (long long)2 * EE, x, eattr, (long long)EE * FF,
        Wk, 272 * 256, HH, bk, HH, p_kb, (long long)EE * HH, HH, EE, HH, 272, 0);
    // v
    gemm_kernel<3, 0><<<dim3(2, gridE, RR), blk>>>(
        nullptr, 0, 0, eidx, (long long)2 * EE, x, eattr, (long long)EE * FF,
        Wv, 272 * 256, HH, bv, HH, p_vb, (long long)EE * HH, HH, EE, HH, 272, 0);

    // edge softmax (3 passes)
    scores_kernel<<<RR * EE / 8, blk>>>(p_qe, p_kb, eidx, prior, p_sc, p_m);
    ex_kernel<<<RR * EE * NHH / 256, blk>>>(eidx, p_m, p_sc, p_den);
    agg_kernel<<<RR * EE / 8, blk>>>(p_sc, p_den, p_vb, eidx, p_agg);

    // rel_out = gelu(agg @ Wm + bm)
    gemm_kernel<0, 1><<<dim3(2, gridN, RR), blk>>>(
        p_agg, (long long)NN * HH, HH, nullptr, 0, nullptr, nullptr, 0,
        Wm, 65536, HH, bm, HH, p_rel, (long long)NN * HH, HH, NN, HH, HH, 0);

    // h = gelu(all_rel @ W_ir1 + b_ir1)   (rel-stacked A loader, K=1536)
    gemm_kernel<1, 1><<<dim3(2, gridN, 1), blk>>>(
        p_rel, 0, 0, nullptr, 0, nullptr, nullptr, 0,
        Wir1, 0, HH, bir1, 0, p_h1, 0, HH, NN, HH, RR * HH, NN);

    // inter softmax + mix + meta paths
    inter_kernel<<<NN, blk>>>(p_h1, Wir2, bir2, p_rel, p_cat, p_paths);

    // stacked = paths @ Wmp + bmp  (z=3, strided A/C)
    gemm_kernel<0, 0><<<dim3(2, gridN, 3), blk>>>(
        p_paths, 256, 768, nullptr, 0, nullptr, nullptr, 0,
        Wmp, 65536, HH, bmp, HH, p_stk, 256, 768, NN, HH, HH, 0);

    // t = tanh(stacked @ Wa1 + ba1)  viewed as [3N,256] @ [256,128]
    gemm_kernel<0, 2><<<dim3(1, grid3N, 1), blk>>>(
        p_stk, 0, HH, nullptr, 0, nullptr, nullptr, 0,
        Wa1, 0, 128, ba1, 0, p_t, 0, 128, 3 * NN, 128, HH, 0);

    // meta attention + LN -> cat[:,256:]
    meta_kernel<<<NN, blk>>>(p_t, Wa2, p_stk, gmeta, bmeta, p_cat);

    // combined = gelu(cat @ Wc + bc)
    gemm_kernel<0, 1><<<dim3(2, gridN, 1), blk>>>(
        p_cat, 0, 2 * HH, nullptr, 0, nullptr, nullptr, 0,
        Wc, 0, HH, bc, 0, p_comb, 0, HH, NN, HH, 2 * HH, 0);

    // out = LN(x + combined)
    out_kernel<<<NN, blk>>>(x, p_comb, gout, bout, out);
}

// round 5
// speedup vs baseline: 1.1205x; 1.1205x over previous
#include <cuda_runtime.h>
#include <math.h>
#include <stdint.h>

#define NN 50000
#define RR 6
#define EE 32768
#define HH 256
#define FF 16
#define NHH 8
#define HDD 32

// ---------------- scratch (device globals; no allocation) ----------------
__device__ float    g_qe  [(size_t)RR*EE*HH];
__device__ float    g_kb  [(size_t)RR*EE*HH];
__device__ float    g_vb  [(size_t)RR*EE*HH];
__device__ float    g_sc  [(size_t)RR*EE*NHH];
__device__ unsigned g_m   [(size_t)RR*NN*NHH];
__device__ float    g_den [(size_t)RR*NN*NHH];
__device__ float    g_agg [(size_t)RR*NN*HH];
__device__ float    g_rel [(size_t)RR*NN*HH];
__device__ float    g_h1  [(size_t)NN*HH];
__device__ float    g_cat [(size_t)NN*2*HH];
__device__ float    g_paths[(size_t)NN*3*HH];
__device__ float    g_stk [(size_t)NN*3*HH];
__device__ float    g_t   [(size_t)NN*3*(HH/2)];
__device__ float    g_comb[(size_t)NN*HH];

// ---------------- helpers ----------------
__device__ __forceinline__ unsigned encodeF(float f) {
    unsigned u = __float_as_uint(f);
    return (u & 0x80000000u) ? ~u : (u | 0x80000000u);
}
__device__ __forceinline__ float decodeF(unsigned u) {
    return (u & 0x80000000u) ? __uint_as_float(u & 0x7fffffffu)
                             : __uint_as_float(~u);
}
__device__ __forceinline__ float gelu_exact(float v) {
    return 0.5f * v * (1.0f + erff(v * 0.7071067811865475f));
}

// packed fp32x2 FMA (FFMA2) — ptxas never emits this from C++; PTX only.
__device__ __forceinline__ void ffma2(unsigned long long& d,
                                      unsigned long long a,
                                      unsigned long long b) {
    asm("fma.rn.f32x2 %0, %1, %2, %3;" : "=l"(d) : "l"(a), "l"(b), "l"(d));
}
__device__ __forceinline__ unsigned long long bcast2(float a) {
    unsigned long long r;
    asm("mov.b64 %0, {%1, %1};" : "=l"(r) : "f"(a));
    return r;
}
__device__ __forceinline__ float2 unpack2(unsigned long long v) {
    float2 f;
    asm("mov.b64 {%0, %1}, %2;" : "=f"(f.x), "=f"(f.y) : "l"(v));
    return f;
}

// ---------------- zero init ----------------
__global__ void zero_kernel() {
    size_t i = (size_t)blockIdx.x * blockDim.x + threadIdx.x;
    if (i < (size_t)RR * NN * HH) g_agg[i] = 0.0f;
    if (i < (size_t)RR * NN * NHH) { g_m[i] = 0u; g_den[i] = 0.0f; }
}

// ---------------- generic tiled SGEMM (FFMA2, BK=16, double-buffered) -----
// C[M,Nn] = act(Aload[M,K] @ B[K,Nn] + bias), batched over blockIdx.z.
// ALOAD: 0 plain (A,lda), 1 relstack, 2 gather x rows by gidx,
//        3 gather x + concat edge_attr (K=272).
// Nn multiple of 128 handled via grid; K must be a multiple of 16.
#define BM 128
#define BN 128
#define BKK 16
#define TM 8
#define TN 8

template<int ALOAD, int ACT>
__global__ __launch_bounds__(256, 2)
void gemm_kernel(const float* __restrict__ A, long long aBatch, int lda,
                 const int*  __restrict__ gidx, long long gBatch,
                 const float* __restrict__ xPtr,
                 const float* __restrict__ eattr, long long eaBatch,
                 const float* __restrict__ B, long long bBatch, int ldb,
                 const float* __restrict__ bias, long long biasBatch,
                 float* __restrict__ C, long long cBatch, int ldc,
                 int M, int Nn, int K, int relM)
{
    const int z = blockIdx.z;
    const float* Bz  = B + (size_t)z * bBatch;
    const float* bz  = bias + (size_t)z * biasBatch;
    float*       Cz  = C + (size_t)z * cBatch;
    const float* Az  = (ALOAD <= 1) ? (A + (size_t)z * aBatch) : nullptr;
    const int*   gz  = (ALOAD >= 2) ? (gidx + (size_t)z * gBatch) : nullptr;
    const float* eaz = (ALOAD == 3) ? (eattr + (size_t)z * eaBatch) : nullptr;

    const int row0 = blockIdx.y * BM;
    const int col0 = blockIdx.x * BN;

    __shared__ __align__(16) float As[2][BKK][BM];
    __shared__ __align__(16) float Bs[2][BKK][BN];

    const int tid  = threadIdx.x;
    // A-load mapping: 128 rows x 16 k; 8 floats (2 float4) per thread
    const int aRow = tid >> 1;           // 0..127
    const int aK8  = (tid & 1) * 8;      // 0 or 8
    // B-load mapping: 16 k x 128 cols; 8 floats (2 float4) per thread
    const int bK   = tid >> 4;           // 0..15
    const int bC8  = (tid & 15) * 8;     // 0..120

    const int rowIdx = row0 + aRow;
    const bool rowOK = rowIdx < M;
    int nodeIdx = 0;
    if (ALOAD >= 2) nodeIdx = rowOK ? gz[rowIdx] : 0;

    const int trow = tid >> 4;   // 0..15
    const int tcol = tid & 15;   // 0..15

    unsigned long long acc[TM][TN / 2];
#pragma unroll
    for (int i = 0; i < TM; i++)
#pragma unroll
        for (int j = 0; j < TN / 2; j++) acc[i][j] = 0ull;

    float4 av0, av1, bv0, bv1;

    auto loadAB = [&](int k0) {
        av0 = make_float4(0.f, 0.f, 0.f, 0.f);
        av1 = av0;
        const int kk = k0 + aK8;
        if (rowOK) {
            if (ALOAD == 0) {
                const float* p = Az + (size_t)rowIdx * lda + kk;
                av0 = *reinterpret_cast<const float4*>(p);
                av1 = *reinterpret_cast<const float4*>(p + 4);
            } else if (ALOAD == 1) {
                const int rel = kk >> 8, cc = kk & 255;
                const float* p = Az + ((size_t)rel * relM + rowIdx) * 256 + cc;
                av0 = *reinterpret_cast<const float4*>(p);
                av1 = *reinterpret_cast<const float4*>(p + 4);
            } else if (ALOAD == 2) {
                const float* p = xPtr + (size_t)nodeIdx * 256 + kk;
                av0 = *reinterpret_cast<const float4*>(p);
                av1 = *reinterpret_cast<const float4*>(p + 4);
            } else {
                if (kk < 256) {
                    const float* p = xPtr + (size_t)nodeIdx * 256 + kk;
                    av0 = *reinterpret_cast<const float4*>(p);
                    av1 = *reinterpret_cast<const float4*>(p + 4);
                } else {
                    const float* p = eaz + (size_t)rowIdx * FF + (kk - 256);
                    av0 = *reinterpret_cast<const float4*>(p);
                    av1 = *reinterpret_cast<const float4*>(p + 4);
                }
            }
        }
        const float* pb = Bz + (size_t)(k0 + bK) * ldb + col0 + bC8;
        bv0 = *reinterpret_cast<const float4*>(pb);
        bv1 = *reinterpret_cast<const float4*>(pb + 4);
    };

    auto storeAB = [&](int buf) {
        As[buf][aK8 + 0][aRow] = av0.x;
        As[buf][aK8 + 1][aRow] = av0.y;
        As[buf][aK8 + 2][aRow] = av0.z;
        As[buf][aK8 + 3][aRow] = av0.w;
        As[buf][aK8 + 4][aRow] = av1.x;
        As[buf][aK8 + 5][aRow] = av1.y;
        As[buf][aK8 + 6][aRow] = av1.z;
        As[buf][aK8 + 7][aRow] = av1.w;
        *reinterpret_cast<float4*>(&Bs[buf][bK][bC8])     = bv0;
        *reinterpret_cast<float4*>(&Bs[buf][bK][bC8 + 4]) = bv1;
    };

    const int nt = K / BKK;
    loadAB(0);
    storeAB(0);
    __syncthreads();

    for (int kt = 0; kt < nt; kt++) {
        const int c = kt & 1;
        if (kt + 1 < nt) loadAB((kt + 1) * BKK);

#pragma unroll
        for (int k2 = 0; k2 < BKK; k2++) {
            const float4 t0 = *reinterpret_cast<const float4*>(&As[c][k2][trow * TM]);
            const float4 t1 = *reinterpret_cast<const float4*>(&As[c][k2][trow * TM + 4]);
            const ulonglong2 q0 = *reinterpret_cast<const ulonglong2*>(&Bs[c][k2][tcol * TN]);
            const ulonglong2 q1 = *reinterpret_cast<const ulonglong2*>(&Bs[c][k2][tcol * TN + 4]);
            const unsigned long long b0 = q0.x, b1 = q0.y, b2 = q1.x, b3 = q1.y;
            float a[8] = {t0.x, t0.y, t0.z, t0.w, t1.x, t1.y, t1.z, t1.w};
#pragma unroll
            for (int i = 0; i < TM; i++) {
                const unsigned long long a2 = bcast2(a[i]);
                ffma2(acc[i][0], a2, b0);
                ffma2(acc[i][1], a2, b1);
                ffma2(acc[i][2], a2, b2);
                ffma2(acc[i][3], a2, b3);
            }
        }
        if (kt + 1 < nt) storeAB((kt + 1) & 1);
        __syncthreads();
    }

#pragma unroll
    for (int i = 0; i < TM; i++) {
        const int r = row0 + trow * TM + i;
        if (r >= M) continue;
#pragma unroll
        for (int j = 0; j < TN / 2; j++) {
            const int cc = col0 + tcol * TN + j * 2;
            float2 f = unpack2(acc[i][j]);
            float v0 = f.x + bz[cc];
            float v1 = f.y + bz[cc + 1];
            if (ACT == 1) { v0 = gelu_exact(v0); v1 = gelu_exact(v1); }
            else if (ACT == 2) { v0 = tanhf(v0); v1 = tanhf(v1); }
            float2 o; o.x = v0; o.y = v1;
            *reinterpret_cast<float2*>(&Cz[(size_t)r * ldc + cc]) = o;
        }
    }
}

// ---------------- edge pass 1: scores + segment max ----------------
__global__ __launch_bounds__(256)
void scores_kernel(const float* __restrict__ qe, const float* __restrict__ kb,
                   const int* __restrict__ eidx, const float* __restrict__ prior,
                   float* __restrict__ sc, unsigned* __restrict__ mEnc)
{
    const int w    = (blockIdx.x * blockDim.x + threadIdx.x) >> 5;  // global edge
    const int lane = threadIdx.x & 31;
    const int r = w >> 15;
    const int e = w & (EE - 1);
    const int dst = eidx[(size_t)r * 2 * EE + EE + e];
    const float* qrow = qe + (size_t)w * HH;
    const float* krow = kb + (size_t)w * HH;
    float s[NHH];
#pragma unroll
    for (int h = 0; h < NHH; h++) {
        float p = qrow[h * HDD + lane] * krow[h * HDD + lane];
#pragma unroll
        for (int o = 16; o; o >>= 1) p += __shfl_xor_sync(0xffffffffu, p, o);
        s[h] = p;
    }
    if (lane == 0) {
#pragma unroll
        for (int h = 0; h < NHH; h++) {
            const float val = s[h] * 0.17677669529663687f * prior[r * NHH + h];
            sc[(size_t)w * NHH + h] = val;
            atomicMax(&mEnc[((size_t)r * NN + dst) * NHH + h], encodeF(val));
        }
    }
}

// ---------------- edge pass 2: exp + segment sum ----------------
__global__ __launch_bounds__(256)
void ex_kernel(const int* __restrict__ eidx, const unsigned* __restrict__ mEnc,
               float* __restrict__ sc, float* __restrict__ den)
{
    const int id = blockIdx.x * blockDim.x + threadIdx.x;  // < RR*EE*NHH
    const int h = id & (NHH - 1);
    const int e = (id >> 3) & (EE - 1);
    const int r = id >> 18;
    const int dst = eidx[(size_t)r * 2 * EE + EE + e];
    const float m = decodeF(mEnc[((size_t)r * NN + dst) * NHH + h]);
    const float ex = expf(sc[id] - m);
    sc[id] = ex;
    atomicAdd(&den[((size_t)r * NN + dst) * NHH + h], ex);
}

// ---------------- edge pass 3: weighted V scatter ----------------
__global__ __launch_bounds__(256)
void agg_kernel(const float* __restrict__ sc, const float* __restrict__ den,
                const float* __restrict__ vb, const int* __restrict__ eidx,
                float* __restrict__ agg)
{
    const int w    = (blockIdx.x * blockDim.x + threadIdx.x) >> 5;
    const int lane = threadIdx.x & 31;
    const int r = w >> 15;
    const int e = w & (EE - 1);
    const int dst = eidx[(size_t)r * 2 * EE + EE + e];
    const float* vrow = vb + (size_t)w * HH;
    float* arow = agg + ((size_t)r * NN + dst) * HH;
#pragma unroll
    for (int h = 0; h < NHH; h++) {
        const float wt = sc[(size_t)w * NHH + h]
                       / (den[((size_t)r * NN + dst) * NHH + h] + 1e-16f);
        atomicAdd(&arow[h * HDD + lane], wt * vrow[h * HDD + lane]);
    }
}

// ---------------- inter-relation softmax mix + meta paths ----------------
__global__ __launch_bounds__(256)
void inter_kernel(const float* __restrict__ h1, const float* __restrict__ Wir2,
                  const float* __restrict__ bir2, const float* __restrict__ rel,
                  float* __restrict__ cat, float* __restrict__ paths)
{
    const int n = blockIdx.x;
    const int tid = threadIdx.x;
    __shared__ float red[256];
    __shared__ float s_logit[RR];
    __shared__ float wsm[RR];

    const float hv = h1[(size_t)n * HH + tid];
    for (int r = 0; r < RR; r++) {
        red[tid] = hv * Wir2[tid * RR + r];
        __syncthreads();
        for (int s = 128; s > 0; s >>= 1) {
            if (tid < s) red[tid] += red[tid + s];
            __syncthreads();
        }
        if (tid == 0) s_logit[r] = red[0] + bir2[r];
        __syncthreads();
    }
    if (tid == 0) {
        float mx = s_logit[0];
        for (int r = 1; r < RR; r++) mx = fmaxf(mx, s_logit[r]);
        float sum = 0.f;
        float ex[RR];
        for (int r = 0; r < RR; r++) { ex[r] = expf(s_logit[r] - mx); sum += ex[r]; }
        for (int r = 0; r < RR; r++) wsm[r] = ex[r] / sum;
    }
    __syncthreads();

    float v[RR];
#pragma unroll
    for (int r = 0; r < RR; r++) v[r] = rel[((size_t)r * NN + n) * HH + tid];
    float inter = 0.f;
#pragma unroll
    for (int r = 0; r < RR; r++) inter += wsm[r] * v[r];
    cat[(size_t)n * 2 * HH + tid] = inter;
    paths[((size_t)n * 3 + 0) * HH + tid] = v[2] + v[3];
    paths[((size_t)n * 3 + 1) * HH + tid] = v[4] + v[0];
    paths[((size_t)n * 3 + 2) * HH + tid] = v[1] + v[5];
}

// ---------------- meta attention + layernorm ----------------
__global__ __launch_bounds__(256)
void meta_kernel(const float* __restrict__ tb, const float* __restrict__ Wa2,
                 const float* __restrict__ stk, const float* __restrict__ gm,
                 const float* __restrict__ bm, float* __restrict__ cat)
{
    const int n = blockIdx.x;
    const int tid = threadIdx.x;
    __shared__ float red[256];
    __shared__ float s_logit[3];
    __shared__ float attn[3];
    __shared__ float s_mu, s_rstd;

    for (int p = 0; p < 3; p++) {
        float pv = 0.f;
        if (tid < 128) pv = tb[(size_t)n * 384 + p * 128 + tid] * Wa2[tid];
        red[tid] = pv;
        __syncthreads();
        for (int s = 128; s > 0; s >>= 1) {
            if (tid < s) red[tid] += red[tid + s];
            __syncthreads();
        }
        if (tid == 0) s_logit[p] = red[0];
        __syncthreads();
    }
    if (tid == 0) {
        float mx = fmaxf(s_logit[0], fmaxf(s_logit[1], s_logit[2]));
        float e0 = expf(s_logit[0] - mx), e1 = expf(s_logit[1] - mx), e2 = expf(s_logit[2] - mx);
        float sum = e0 + e1 + e2;
        attn[0] = e0 / sum; attn[1] = e1 / sum; attn[2] = e2 / sum;
    }
    __syncthreads();

    float mp = attn[0] * stk[((size_t)n * 3 + 0) * HH + tid]
             + attn[1] * stk[((size_t)n * 3 + 1) * HH + tid]
             + attn[2] * stk[((size_t)n * 3 + 2) * HH + tid];

    red[tid] = mp;
    __syncthreads();
    for (int s = 128; s > 0; s >>= 1) { if (tid < s) red[tid] += red[tid + s]; __syncthreads(); }
    if (tid == 0) s_mu = red[0] / (float)HH;
    __syncthreads();
    const float d = mp - s_mu;
    red[tid] = d * d;
    __syncthreads();
    for (int s = 128; s > 0; s >>= 1) { if (tid < s) red[tid] += red[tid + s]; __syncthreads(); }
    if (tid == 0) s_rstd = rsqrtf(red[0] / (float)HH + 1e-5f);
    __syncthreads();

    cat[(size_t)n * 2 * HH + HH + tid] = d * s_rstd * gm[tid] + bm[tid];
}

// ---------------- final residual + layernorm ----------------
__global__ __launch_bounds__(256)
void out_kernel(const float* __restrict__ x, const float* __restrict__ comb,
                const float* __restrict__ g, const float* __restrict__ b,
                float* __restrict__ out)
{
    const int n = blockIdx.x;
    const int tid = threadIdx.x;
    __shared__ float red[256];
    __shared__ float s_mu, s_rstd;

    const float y = x[(size_t)n * HH + tid] + comb[(size_t)n * HH + tid];
    red[tid] = y;
    __syncthreads();
    for (int s = 128; s > 0; s >>= 1) { if (tid < s) red[tid] += red[tid + s]; __syncthreads(); }
    if (tid == 0) s_mu = red[0] / (float)HH;
    __syncthreads();
    const float d = y - s_mu;
    red[tid] = d * d;
    __syncthreads();
    for (int s = 128; s > 0; s >>= 1) { if (tid < s) red[tid] += red[tid + s]; __syncthreads(); }
    if (tid == 0) s_rstd = rsqrtf(red[0] / (float)HH + 1e-5f);
    __syncthreads();

    out[(size_t)n * HH + tid] = d * s_rstd * g[tid] + b[tid];
}

// ---------------- launch ----------------
extern "C" void kernel_launch(void* const* d_in, const int* in_sizes, int n_in,
                              void* d_out, int out_size)
{
    (void)in_sizes; (void)n_in; (void)out_size;
    const float* x     = (const float*)d_in[0];
    const int*   eidx  = (const int*)  d_in[1];
    const float* eattr = (const float*)d_in[2];
    const float* Wq    = (const float*)d_in[3];
    const float* bq    = (const float*)d_in[4];
    const float* Wk    = (const float*)d_in[5];
    const float* bk    = (const float*)d_in[6];
    const float* Wv    = (const float*)d_in[7];
    const float* bv    = (const float*)d_in[8];
    const float* prior = (const float*)d_in[9];
    const float* Wm    = (const float*)d_in[10];
    const float* bm    = (const float*)d_in[11];
    const float* Wir1  = (const float*)d_in[12];
    const float* bir1  = (const float*)d_in[13];
    const float* Wir2  = (const float*)d_in[14];
    const float* bir2  = (const float*)d_in[15];
    const float* Wmp   = (const float*)d_in[16];
    const float* bmp   = (const float*)d_in[17];
    const float* Wa1   = (const float*)d_in[18];
    const float* ba1   = (const float*)d_in[19];
    const float* Wa2   = (const float*)d_in[20];
    const float* gmeta = (const float*)d_in[21];
    const float* bmeta = (const float*)d_in[22];
    const float* Wc    = (const float*)d_in[23];
    const float* bc    = (const float*)d_in[24];
    const float* gout  = (const float*)d_in[25];
    const float* bout  = (const float*)d_in[26];
    float* out = (float*)d_out;

    float *p_qe, *p_kb, *p_vb, *p_sc, *p_den, *p_agg, *p_rel, *p_h1,
          *p_cat, *p_paths, *p_stk, *p_t, *p_comb;
    unsigned* p_m;
    cudaGetSymbolAddress((void**)&p_qe,   g_qe);
    cudaGetSymbolAddress((void**)&p_kb,   g_kb);
    cudaGetSymbolAddress((void**)&p_vb,   g_vb);
    cudaGetSymbolAddress((void**)&p_sc,   g_sc);
    cudaGetSymbolAddress((void**)&p_m,    g_m);
    cudaGetSymbolAddress((void**)&p_den,  g_den);
    cudaGetSymbolAddress((void**)&p_agg,  g_agg);
    cudaGetSymbolAddress((void**)&p_rel,  g_rel);
    cudaGetSymbolAddress((void**)&p_h1,   g_h1);
    cudaGetSymbolAddress((void**)&p_cat,  g_cat);
    cudaGetSymbolAddress((void**)&p_paths,g_paths);
    cudaGetSymbolAddress((void**)&p_stk,  g_stk);
    cudaGetSymbolAddress((void**)&p_t,    g_t);
    cudaGetSymbolAddress((void**)&p_comb, g_comb);

    const dim3 blk(256);
    const int gridN = (NN + BM - 1) / BM;          // 391
    const int gridE = EE / BM;                     // 256
    const int grid3N = (3 * NN + BM - 1) / BM;     // 1172

    // zero m/den/agg
    zero_kernel<<<(RR * NN * HH + 255) / 256, blk>>>();

    // q = x[dst] @ Wq + bq    [per relation]
    gemm_kernel<2, 0><<<dim3(2, gridE, RR), blk>>>(
        nullptr, 0, 0, eidx + EE, (long long)2 * EE, x, nullptr, 0,
        Wq, 65536, HH, bq, HH, p_qe, (long long)EE * HH, HH, EE, HH, HH, 0);
    // k = [x[src] | eattr] @ Wk + bk   (K=272 = 17*16)
    gemm_kernel<3, 0><<<dim3(2, gridE, RR), blk>>>(
        nullptr, 0, 0, eidx, (long long)2 * EE, x, eattr, (long long)EE * FF,
        Wk, 272 * 256, HH, bk, HH, p_kb, (long long)EE * HH, HH, EE, HH, 272, 0);
    // v
    gemm_kernel<3, 0><<<dim3(2, gridE, RR), blk>>>(
        nullptr, 0, 0, eidx, (long long)2 * EE, x, eattr, (long long)EE * FF,
        Wv, 272 * 256, HH, bv, HH, p_vb, (long long)EE * HH, HH, EE, HH, 272, 0);

    // edge softmax (3 passes)
    scores_kernel<<<RR * EE / 8, blk>>>(p_qe, p_kb, eidx, prior, p_sc, p_m);
    ex_kernel<<<RR * EE * NHH / 256, blk>>>(eidx, p_m, p_sc, p_den);
    agg_kernel<<<RR * EE / 8, blk>>>(p_sc, p_den, p_vb, eidx, p_agg);

    // rel_out = gelu(agg @ Wm + bm)
    gemm_kernel<0, 1><<<dim3(2, gridN, RR), blk>>>(
        p_agg, (long long)NN * HH, HH, nullptr, 0, nullptr, nullptr, 0,
        Wm, 65536, HH, bm, HH, p_rel, (long long)NN * HH, HH, NN, HH, HH, 0);

    // h = gelu(all_rel @ W_ir1 + b_ir1)   (rel-stacked A loader, K=1536)
    gemm_kernel<1, 1><<<dim3(2, gridN, 1), blk>>>(
        p_rel, 0, 0, nullptr, 0, nullptr, nullptr, 0,
        Wir1, 0, HH, bir1, 0, p_h1, 0, HH, NN, HH, RR * HH, NN);

    // inter softmax + mix + meta paths
    inter_kernel<<<NN, blk>>>(p_h1, Wir2, bir2, p_rel, p_cat, p_paths);

    // stacked = paths @ Wmp + bmp  (z=3, strided A/C)
    gemm_kernel<0, 0><<<dim3(2, gridN, 3), blk>>>(
        p_paths, 256, 768, nullptr, 0, nullptr, nullptr, 0,
        Wmp, 65536, HH, bmp, HH, p_stk, 256, 768, NN, HH, HH, 0);

    // t = tanh(stacked @ Wa1 + ba1)  viewed as [3N,256] @ [256,128]
    gemm_kernel<0, 2><<<dim3(1, grid3N, 1), blk>>>(
        p_stk, 0, HH, nullptr, 0, nullptr, nullptr, 0,
        Wa1, 0, 128, ba1, 0, p_t, 0, 128, 3 * NN, 128, HH, 0);

    // meta attention + LN -> cat[:,256:]
    meta_kernel<<<NN, blk>>>(p_t, Wa2, p_stk, gmeta, bmeta, p_cat);

    // combined = gelu(cat @ Wc + bc)
    gemm_kernel<0, 1><<<dim3(2, gridN, 1), blk>>>(
        p_cat, 0, 2 * HH, nullptr, 0, nullptr, nullptr, 0,
        Wc, 0, HH, bc, 0, p_comb, 0, HH, NN, HH, 2 * HH, 0);

    // out = LN(x + combined)
    out_kernel<<<NN, blk>>>(x, p_comb, gout, bout, out);
}

// round 6
// speedup vs baseline: 2.2170x; 1.9786x over previous
#include <cuda_runtime.h>
#include <cuda_bf16.h>
#include <math.h>
#include <stdint.h>

#define NN 50000
#define RR 6
#define EE 32768
#define HH 256
#define FF 16
#define NHH 8
#define HDD 32

// ---------------- scratch (device globals; no allocation) ----------------
__device__ float    g_qe  [(size_t)RR*EE*HH];
__device__ float    g_kb  [(size_t)RR*EE*HH];
__device__ float    g_vb  [(size_t)RR*EE*HH];
__device__ float    g_sc  [(size_t)RR*EE*NHH];
__device__ unsigned g_m   [(size_t)RR*NN*NHH];
__device__ float    g_den [(size_t)RR*NN*NHH];
__device__ float    g_agg [(size_t)RR*NN*HH];
__device__ float    g_rel [(size_t)RR*NN*HH];
__device__ float    g_h1  [(size_t)NN*HH];
__device__ float    g_cat [(size_t)NN*2*HH];
__device__ float    g_paths[(size_t)NN*3*HH];
__device__ float    g_stk [(size_t)NN*3*HH];
__device__ float    g_t   [(size_t)NN*3*(HH/2)];
__device__ float    g_comb[(size_t)NN*HH];

// converted weights: packed (hi,lo) bf16 pairs, same [K][N] layout as fp32
#define OFF_WQ   0
#define OFF_WK   393216
#define OFF_WV   811008
#define OFF_WM   1228800
#define OFF_WIR1 1622016
#define OFF_WMP  2015232
#define OFF_WA1  2211840
#define OFF_WC   2244608
#define WCVT_TOT 2375680
__device__ __nv_bfloat162 g_wcvt[WCVT_TOT];

// ---------------- helpers ----------------
__device__ __forceinline__ unsigned encodeF(float f) {
    unsigned u = __float_as_uint(f);
    return (u & 0x80000000u) ? ~u : (u | 0x80000000u);
}
__device__ __forceinline__ float decodeF(unsigned u) {
    return (u & 0x80000000u) ? __uint_as_float(u & 0x7fffffffu)
                             : __uint_as_float(~u);
}
__device__ __forceinline__ float gelu_exact(float v) {
    return 0.5f * v * (1.0f + erff(v * 0.7071067811865475f));
}
__device__ __forceinline__ void f2hl(float x, __nv_bfloat16& h, __nv_bfloat16& l) {
    h = __float2bfloat16(x);
    l = __float2bfloat16(x - __bfloat162float(h));
}
__device__ __forceinline__ uint32_t cvta_s(const void* p) {
    return static_cast<uint32_t>(__cvta_generic_to_shared(p));
}

#define LDSM4(r, addr) \
    asm volatile("ldmatrix.sync.aligned.m8n8.x4.shared.b16 {%0,%1,%2,%3},[%4];" \
        : "=r"((r)[0]), "=r"((r)[1]), "=r"((r)[2]), "=r"((r)[3]) : "r"(addr))
#define LDSM4T(r, addr) \
    asm volatile("ldmatrix.sync.aligned.m8n8.x4.trans.shared.b16 {%0,%1,%2,%3},[%4];" \
        : "=r"((r)[0]), "=r"((r)[1]), "=r"((r)[2]), "=r"((r)[3]) : "r"(addr))
#define MMA16816(d, a, b) \
    asm volatile("mma.sync.aligned.m16n8k16.row.col.f32.bf16.bf16.f32 " \
        "{%0,%1,%2,%3},{%4,%5,%6,%7},{%8,%9},{%0,%1,%2,%3};" \
        : "+f"((d)[0]), "+f"((d)[1]), "+f"((d)[2]), "+f"((d)[3]) \
        : "r"((a)[0]), "r"((a)[1]), "r"((a)[2]), "r"((a)[3]), \
          "r"((b)[0]), "r"((b)[1]))

// ---------------- zero init ----------------
__global__ void zero_kernel() {
    size_t i = (size_t)blockIdx.x * blockDim.x + threadIdx.x;
    if (i < (size_t)RR * NN * HH) g_agg[i] = 0.0f;
    if (i < (size_t)RR * NN * NHH) { g_m[i] = 0u; g_den[i] = 0.0f; }
}

// ---------------- weight conversion fp32 -> (hi,lo) bf16 ----------------
__global__ void wconv_kernel(const float* __restrict__ w, int n, int off) {
    int i = blockIdx.x * blockDim.x + threadIdx.x;
    if (i < n) {
        float x = w[i];
        __nv_bfloat16 h, l;
        f2hl(x, h, l);
        __nv_bfloat162 v; v.x = h; v.y = l;
        g_wcvt[off + i] = v;
    }
}

// ---------------- tensor-core split-bf16 GEMM ----------------
// C[M,Nn] = act(A[M,K] @ B[K,Nn] + bias); block tile 128x128, warp 64x32.
// ALOAD: 0 plain, 1 relstack, 2 gather-x, 3 gather-x + eattr concat (K=272).
// B is packed (hi,lo) bf162 in [K][Nn] layout. K % 16 == 0, Nn % 128 == 0.
#define BM 128
#define BN 128

template<int ALOAD, int ACT>
__global__ __launch_bounds__(256)
void gemm_tc(const float* __restrict__ A, long long aBatch, int lda,
             const int*  __restrict__ gidx, long long gBatch,
             const float* __restrict__ xPtr,
             const float* __restrict__ eattr, long long eaBatch,
             const __nv_bfloat162* __restrict__ B, long long bBatch, int ldb,
             const float* __restrict__ bias, long long biasBatch,
             float* __restrict__ C, long long cBatch, int ldc,
             int M, int Nn, int K, int relM)
{
    const int z = blockIdx.z;
    const __nv_bfloat162* Bz = B + (size_t)z * bBatch;
    const float* bz  = bias + (size_t)z * biasBatch;
    float*       Cz  = C + (size_t)z * cBatch;
    const float* Az  = (ALOAD <= 1) ? (A + (size_t)z * aBatch) : nullptr;
    const int*   gz  = (ALOAD >= 2) ? (gidx + (size_t)z * gBatch) : nullptr;
    const float* eaz = (ALOAD == 3) ? (eattr + (size_t)z * eaBatch) : nullptr;

    const int row0 = blockIdx.y * BM;
    const int col0 = blockIdx.x * BN;

    // padded smem: A rows of 16 bf16 padded to 24; B rows of 128 padded to 136
    __shared__ __align__(16) __nv_bfloat16 sA[2][2][BM][24];
    __shared__ __align__(16) __nv_bfloat16 sB[2][2][16][136];

    const int tid  = threadIdx.x;
    const int wid  = tid >> 5;
    const int lane = tid & 31;

    // loader mapping
    const int aRow = tid >> 1;          // 0..127
    const int aK8  = (tid & 1) * 8;     // 0 or 8
    const int bK   = tid >> 4;          // 0..15
    const int bC8  = (tid & 15) * 8;    // 0..120

    const int rowIdx = row0 + aRow;
    const bool rowOK = rowIdx < M;
    int nodeIdx = 0;
    if (ALOAD >= 2) nodeIdx = rowOK ? gz[rowIdx] : 0;

    // mma mapping
    const int warp_m = (wid & 1) * 64;
    const int warp_n = (wid >> 1) * 32;
    const int groupID = lane >> 2;
    const int tig = lane & 3;

    const int aRowL = (lane & 7) | (((lane >> 3) & 1) << 3);   // 0..15
    const int aKofL = ((lane >> 4) & 1) * 8;
    const int bKrowL = (lane & 7) | (((lane >> 3) & 1) << 3);  // 0..15
    const int bNcolL = warp_n + ((lane >> 4) & 1) * 8;

    const uint32_t aBase = cvta_s(&sA[0][0][0][0]);
    const uint32_t bBase = cvta_s(&sB[0][0][0][0]);
    // byte offsets
    const uint32_t aThr = aBase + (uint32_t)(((warp_m + aRowL) * 24 + aKofL) * 2);
    const uint32_t bThr = bBase + (uint32_t)((bKrowL * 136 + bNcolL) * 2);
    const uint32_t A_HL = 128u * 24u * 2u;       // bytes per (hl) plane of A
    const uint32_t B_HL = 16u * 136u * 2u;       // bytes per (hl) plane of B

    float acc[4][4][4];
#pragma unroll
    for (int mi = 0; mi < 4; mi++)
#pragma unroll
        for (int nj = 0; nj < 4; nj++)
#pragma unroll
            for (int r = 0; r < 4; r++) acc[mi][nj][r] = 0.0f;

    float4 av0, av1;
    uint4 bu0, bu1;

    auto loadG = [&](int k0) {
        av0 = make_float4(0.f, 0.f, 0.f, 0.f);
        av1 = av0;
        const int kk = k0 + aK8;
        if (rowOK) {
            if (ALOAD == 0) {
                const float* p = Az + (size_t)rowIdx * lda + kk;
                av0 = *reinterpret_cast<const float4*>(p);
                av1 = *reinterpret_cast<const float4*>(p + 4);
            } else if (ALOAD == 1) {
                const int rel = kk >> 8, cc = kk & 255;
                const float* p = Az + ((size_t)rel * relM + rowIdx) * 256 + cc;
                av0 = *reinterpret_cast<const float4*>(p);
                av1 = *reinterpret_cast<const float4*>(p + 4);
            } else if (ALOAD == 2) {
                const float* p = xPtr + (size_t)nodeIdx * 256 + kk;
                av0 = *reinterpret_cast<const float4*>(p);
                av1 = *reinterpret_cast<const float4*>(p + 4);
            } else {
                if (kk < 256) {
                    const float* p = xPtr + (size_t)nodeIdx * 256 + kk;
                    av0 = *reinterpret_cast<const float4*>(p);
                    av1 = *reinterpret_cast<const float4*>(p + 4);
                } else {
                    const float* p = eaz + (size_t)rowIdx * FF + (kk - 256);
                    av0 = *reinterpret_cast<const float4*>(p);
                    av1 = *reinterpret_cast<const float4*>(p + 4);
                }
            }
        }
        const __nv_bfloat162* pb = Bz + (size_t)(k0 + bK) * ldb + col0 + bC8;
        bu0 = *reinterpret_cast<const uint4*>(pb);
        bu1 = *reinterpret_cast<const uint4*>(pb + 4);
    };

    auto storeS = [&](int buf) {
        float af[8] = {av0.x, av0.y, av0.z, av0.w, av1.x, av1.y, av1.z, av1.w};
#pragma unroll
        for (int i = 0; i < 8; i++) {
            __nv_bfloat16 h, l;
            f2hl(af[i], h, l);
            sA[buf][0][aRow][aK8 + i] = h;
            sA[buf][1][aRow][aK8 + i] = l;
        }
        const __nv_bfloat162* be0 = reinterpret_cast<const __nv_bfloat162*>(&bu0);
        const __nv_bfloat162* be1 = reinterpret_cast<const __nv_bfloat162*>(&bu1);
#pragma unroll
        for (int i = 0; i < 4; i++) {
            sB[buf][0][bK][bC8 + i] = be0[i].x;
            sB[buf][1][bK][bC8 + i] = be0[i].y;
            sB[buf][0][bK][bC8 + 4 + i] = be1[i].x;
            sB[buf][1][bK][bC8 + 4 + i] = be1[i].y;
        }
    };

    const int nt = K / 16;
    loadG(0);
    storeS(0);
    __syncthreads();

    for (int kt = 0; kt < nt; kt++) {
        const int c = kt & 1;
        if (kt + 1 < nt) loadG((kt + 1) * 16);

        // B fragments: [hl][nj][2]
        uint32_t bfr[2][4][2];
#pragma unroll
        for (int hl = 0; hl < 2; hl++) {
            const uint32_t base = bThr + (uint32_t)(c * 2 + hl) * B_HL;
#pragma unroll
            for (int p = 0; p < 2; p++) {
                uint32_t t4[4];
                LDSM4T(t4, base + p * 32u);
                bfr[hl][2 * p][0] = t4[0];
                bfr[hl][2 * p][1] = t4[1];
                bfr[hl][2 * p + 1][0] = t4[2];
                bfr[hl][2 * p + 1][1] = t4[3];
            }
        }
#pragma unroll
        for (int mi = 0; mi < 4; mi++) {
            uint32_t ah[4], al[4];
            const uint32_t abufs = aThr + (uint32_t)(c * 2) * A_HL
                                 + (uint32_t)(mi * 16 * 24 * 2);
            LDSM4(ah, abufs);
            LDSM4(al, abufs + A_HL);
#pragma unroll
            for (int nj = 0; nj < 4; nj++) {
                MMA16816(acc[mi][nj], ah, bfr[0][nj]);
                MMA16816(acc[mi][nj], ah, bfr[1][nj]);
                MMA16816(acc[mi][nj], al, bfr[0][nj]);
            }
        }
        if (kt + 1 < nt) storeS((kt + 1) & 1);
        __syncthreads();
    }

    // epilogue
#pragma unroll
    for (int mi = 0; mi < 4; mi++) {
#pragma unroll
        for (int half = 0; half < 2; half++) {
            const int r = row0 + warp_m + mi * 16 + groupID + half * 8;
            if (r >= M) continue;
#pragma unroll
            for (int nj = 0; nj < 4; nj++) {
                const int cc = col0 + warp_n + nj * 8 + tig * 2;
                float v0 = acc[mi][nj][half * 2 + 0] + bz[cc];
                float v1 = acc[mi][nj][half * 2 + 1] + bz[cc + 1];
                if (ACT == 1) { v0 = gelu_exact(v0); v1 = gelu_exact(v1); }
                else if (ACT == 2) { v0 = tanhf(v0); v1 = tanhf(v1); }
                float2 o; o.x = v0; o.y = v1;
                *reinterpret_cast<float2*>(&Cz[(size_t)r * ldc + cc]) = o;
            }
        }
    }
}

// ---------------- edge pass 1: scores + segment max ----------------
__global__ __launch_bounds__(256)
void scores_kernel(const float* __restrict__ qe, const float* __restrict__ kb,
                   const int* __restrict__ eidx, const float* __restrict__ prior,
                   float* __restrict__ sc, unsigned* __restrict__ mEnc)
{
    const int w    = (blockIdx.x * blockDim.x + threadIdx.x) >> 5;
    const int lane = threadIdx.x & 31;
    const int r = w >> 15;
    const int e = w & (EE - 1);
    const int dst = eidx[(size_t)r * 2 * EE + EE + e];
    const float* qrow = qe + (size_t)w * HH;
    const float* krow = kb + (size_t)w * HH;
    float s[NHH];
#pragma unroll
    for (int h = 0; h < NHH; h++) {
        float p = qrow[h * HDD + lane] * krow[h * HDD + lane];
#pragma unroll
        for (int o = 16; o; o >>= 1) p += __shfl_xor_sync(0xffffffffu, p, o);
        s[h] = p;
    }
    if (lane == 0) {
#pragma unroll
        for (int h = 0; h < NHH; h++) {
            const float val = s[h] * 0.17677669529663687f * prior[r * NHH + h];
            sc[(size_t)w * NHH + h] = val;
            atomicMax(&mEnc[((size_t)r * NN + dst) * NHH + h], encodeF(val));
        }
    }
}

// ---------------- edge pass 2: exp + segment sum ----------------
__global__ __launch_bounds__(256)
void ex_kernel(const int* __restrict__ eidx, const unsigned* __restrict__ mEnc,
               float* __restrict__ sc, float* __restrict__ den)
{
    const int id = blockIdx.x * blockDim.x + threadIdx.x;
    const int h = id & (NHH - 1);
    const int e = (id >> 3) & (EE - 1);
    const int r = id >> 18;
    const int dst = eidx[(size_t)r * 2 * EE + EE + e];
    const float m = decodeF(mEnc[((size_t)r * NN + dst) * NHH + h]);
    const float ex = expf(sc[id] - m);
    sc[id] = ex;
    atomicAdd(&den[((size_t)r * NN + dst) * NHH + h], ex);
}

// ---------------- edge pass 3: weighted V scatter ----------------
__global__ __launch_bounds__(256)
void agg_kernel(const float* __restrict__ sc, const float* __restrict__ den,
                const float* __restrict__ vb, const int* __restrict__ eidx,
                float* __restrict__ agg)
{
    const int w    = (blockIdx.x * blockDim.x + threadIdx.x) >> 5;
    const int lane = threadIdx.x & 31;
    const int r = w >> 15;
    const int e = w & (EE - 1);
    const int dst = eidx[(size_t)r * 2 * EE + EE + e];
    const float* vrow = vb + (size_t)w * HH;
    float* arow = agg + ((size_t)r * NN + dst) * HH;
#pragma unroll
    for (int h = 0; h < NHH; h++) {
        const float wt = sc[(size_t)w * NHH + h]
                       / (den[((size_t)r * NN + dst) * NHH + h] + 1e-16f);
        atomicAdd(&arow[h * HDD + lane], wt * vrow[h * HDD + lane]);
    }
}

// ---------------- inter-relation softmax mix + meta paths ----------------
__global__ __launch_bounds__(256)
void inter_kernel(const float* __restrict__ h1, const float* __restrict__ Wir2,
                  const float* __restrict__ bir2, const float* __restrict__ rel,
                  float* __restrict__ cat, float* __restrict__ paths)
{
    const int n = blockIdx.x;
    const int tid = threadIdx.x;
    __shared__ float red[256];
    __shared__ float s_logit[RR];
    __shared__ float wsm[RR];

    const float hv = h1[(size_t)n * HH + tid];
    for (int r = 0; r < RR; r++) {
        red[tid] = hv * Wir2[tid * RR + r];
        __syncthreads();
        for (int s = 128; s > 0; s >>= 1) {
            if (tid < s) red[tid] += red[tid + s];
            __syncthreads();
        }
        if (tid == 0) s_logit[r] = red[0] + bir2[r];
        __syncthreads();
    }
    if (tid == 0) {
        float mx = s_logit[0];
        for (int r = 1; r < RR; r++) mx = fmaxf(mx, s_logit[r]);
        float sum = 0.f;
        float ex[RR];
        for (int r = 0; r < RR; r++) { ex[r] = expf(s_logit[r] - mx); sum += ex[r]; }
        for (int r = 0; r < RR; r++) wsm[r] = ex[r] / sum;
    }
    __syncthreads();

    float v[RR];
#pragma unroll
    for (int r = 0; r < RR; r++) v[r] = rel[((size_t)r * NN + n) * HH + tid];
    float inter = 0.f;
#pragma unroll
    for (int r = 0; r < RR; r++) inter += wsm[r] * v[r];
    cat[(size_t)n * 2 * HH + tid] = inter;
    paths[((size_t)n * 3 + 0) * HH + tid] = v[2] + v[3];
    paths[((size_t)n * 3 + 1) * HH + tid] = v[4] + v[0];
    paths[((size_t)n * 3 + 2) * HH + tid] = v[1] + v[5];
}

// ---------------- meta attention + layernorm ----------------
__global__ __launch_bounds__(256)
void meta_kernel(const float* __restrict__ tb, const float* __restrict__ Wa2,
                 const float* __restrict__ stk, const float* __restrict__ gm,
                 const float* __restrict__ bm, float* __restrict__ cat)
{
    const int n = blockIdx.x;
    const int tid = threadIdx.x;
    __shared__ float red[256];
    __shared__ float s_logit[3];
    __shared__ float attn[3];
    __shared__ float s_mu, s_rstd;

    for (int p = 0; p < 3; p++) {
        float pv = 0.f;
        if (tid < 128) pv = tb[(size_t)n * 384 + p * 128 + tid] * Wa2[tid];
        red[tid] = pv;
        __syncthreads();
        for (int s = 128; s > 0; s >>= 1) {
            if (tid < s) red[tid] += red[tid + s];
            __syncthreads();
        }
        if (tid == 0) s_logit[p] = red[0];
        __syncthreads();
    }
    if (tid == 0) {
        float mx = fmaxf(s_logit[0], fmaxf(s_logit[1], s_logit[2]));
        float e0 = expf(s_logit[0] - mx), e1 = expf(s_logit[1] - mx), e2 = expf(s_logit[2] - mx);
        float sum = e0 + e1 + e2;
        attn[0] = e0 / sum; attn[1] = e1 / sum; attn[2] = e2 / sum;
    }
    __syncthreads();

    float mp = attn[0] * stk[((size_t)n * 3 + 0) * HH + tid]
             + attn[1] * stk[((size_t)n * 3 + 1) * HH + tid]
             + attn[2] * stk[((size_t)n * 3 + 2) * HH + tid];

    red[tid] = mp;
    __syncthreads();
    for (int s = 128; s > 0; s >>= 1) { if (tid < s) red[tid] += red[tid + s]; __syncthreads(); }
    if (tid == 0) s_mu = red[0] / (float)HH;
    __syncthreads();
    const float d = mp - s_mu;
    red[tid] = d * d;
    __syncthreads();
    for (int s = 128; s > 0; s >>= 1) { if (tid < s) red[tid] += red[tid + s]; __syncthreads(); }
    if (tid == 0) s_rstd = rsqrtf(red[0] / (float)HH + 1e-5f);
    __syncthreads();

    cat[(size_t)n * 2 * HH + HH + tid] = d * s_rstd * gm[tid] + bm[tid];
}

// ---------------- final residual + layernorm ----------------
__global__ __launch_bounds__(256)
void out_kernel(const float* __restrict__ x, const float* __restrict__ comb,
                const float* __restrict__ g, const float* __restrict__ b,
                float* __restrict__ out)
{
    const int n = blockIdx.x;
    const int tid = threadIdx.x;
    __shared__ float red[256];
    __shared__ float s_mu, s_rstd;

    const float y = x[(size_t)n * HH + tid] + comb[(size_t)n * HH + tid];
    red[tid] = y;
    __syncthreads();
    for (int s = 128; s > 0; s >>= 1) { if (tid < s) red[tid] += red[tid + s]; __syncthreads(); }
    if (tid == 0) s_mu = red[0] / (float)HH;
    __syncthreads();
    const float d = y - s_mu;
    red[tid] = d * d;
    __syncthreads();
    for (int s = 128; s > 0; s >>= 1) { if (tid < s) red[tid] += red[tid + s]; __syncthreads(); }
    if (tid == 0) s_rstd = rsqrtf(red[0] / (float)HH + 1e-5f);
    __syncthreads();

    out[(size_t)n * HH + tid] = d * s_rstd * g[tid] + b[tid];
}

// ---------------- launch ----------------
extern "C" void kernel_launch(void* const* d_in, const int* in_sizes, int n_in,
                              void* d_out, int out_size)
{
    (void)in_sizes; (void)n_in; (void)out_size;
    const float* x     = (const float*)d_in[0];
    const int*   eidx  = (const int*)  d_in[1];
    const float* eattr = (const float*)d_in[2];
    const float* Wq    = (const float*)d_in[3];
    const float* bq    = (const float*)d_in[4];
    const float* Wk    = (const float*)d_in[5];
    const float* bk    = (const float*)d_in[6];
    const float* Wv    = (const float*)d_in[7];
    const float* bv    = (const float*)d_in[8];
    const float* prior = (const float*)d_in[9];
    const float* Wm    = (const float*)d_in[10];
    const float* bm    = (const float*)d_in[11];
    const float* Wir1  = (const float*)d_in[12];
    const float* bir1  = (const float*)d_in[13];
    const float* Wir2  = (const float*)d_in[14];
    const float* bir2  = (const float*)d_in[15];
    const float* Wmp   = (const float*)d_in[16];
    const float* bmp   = (const float*)d_in[17];
    const float* Wa1   = (const float*)d_in[18];
    const float* ba1   = (const float*)d_in[19];
    const float* Wa2   = (const float*)d_in[20];
    const float* gmeta = (const float*)d_in[21];
    const float* bmeta = (const float*)d_in[22];
    const float* Wc    = (const float*)d_in[23];
    const float* bc    = (const float*)d_in[24];
    const float* gout  = (const float*)d_in[25];
    const float* bout  = (const float*)d_in[26];
    float* out = (float*)d_out;

    float *p_qe, *p_kb, *p_vb, *p_sc, *p_den, *p_agg, *p_rel, *p_h1,
          *p_cat, *p_paths, *p_stk, *p_t, *p_comb;
    unsigned* p_m;
    __nv_bfloat162* p_w;
    cudaGetSymbolAddress((void**)&p_qe,   g_qe);
    cudaGetSymbolAddress((void**)&p_kb,   g_kb);
    cudaGetSymbolAddress((void**)&p_vb,   g_vb);
    cudaGetSymbolAddress((void**)&p_sc,   g_sc);
    cudaGetSymbolAddress((void**)&p_m,    g_m);
    cudaGetSymbolAddress((void**)&p_den,  g_den);
    cudaGetSymbolAddress((void**)&p_agg,  g_agg);
    cudaGetSymbolAddress((void**)&p_rel,  g_rel);
    cudaGetSymbolAddress((void**)&p_h1,   g_h1);
    cudaGetSymbolAddress((void**)&p_cat,  g_cat);
    cudaGetSymbolAddress((void**)&p_paths,g_paths);
    cudaGetSymbolAddress((void**)&p_stk,  g_stk);
    cudaGetSymbolAddress((void**)&p_t,    g_t);
    cudaGetSymbolAddress((void**)&p_comb, g_comb);
    cudaGetSymbolAddress((void**)&p_w,    g_wcvt);

    const dim3 blk(256);
    const int gridN = (NN + BM - 1) / BM;          // 391
    const int gridE = EE / BM;                     // 256
    const int grid3N = (3 * NN + BM - 1) / BM;     // 1172

    // zero m/den/agg
    zero_kernel<<<(RR * NN * HH + 255) / 256, blk>>>();

    // convert all weights fp32 -> (hi,lo) bf16 pairs
    wconv_kernel<<<(RR * 65536 + 255) / 256, blk>>>(Wq,   RR * 65536, OFF_WQ);
    wconv_kernel<<<(RR * 69632 + 255) / 256, blk>>>(Wk,   RR * 69632, OFF_WK);
    wconv_kernel<<<(RR * 69632 + 255) / 256, blk>>>(Wv,   RR * 69632, OFF_WV);
    wconv_kernel<<<(RR * 65536 + 255) / 256, blk>>>(Wm,   RR * 65536, OFF_WM);
    wconv_kernel<<<(1536 * 256 + 255) / 256, blk>>>(Wir1, 1536 * 256, OFF_WIR1);
    wconv_kernel<<<(3 * 65536 + 255) / 256, blk>>>(Wmp,  3 * 65536, OFF_WMP);
    wconv_kernel<<<(256 * 128 + 255) / 256, blk>>>(Wa1,  256 * 128, OFF_WA1);
    wconv_kernel<<<(512 * 256 + 255) / 256, blk>>>(Wc,   512 * 256, OFF_WC);

    // q = x[dst] @ Wq + bq    [per relation]
    gemm_tc<2, 0><<<dim3(2, gridE, RR), blk>>>(
        nullptr, 0, 0, eidx + EE, (long long)2 * EE, x, nullptr, 0,
        p_w + OFF_WQ, 65536, HH, bq, HH, p_qe, (long long)EE * HH, HH,
        EE, HH, HH, 0);
    // k = [x[src] | eattr] @ Wk + bk   (K=272)
    gemm_tc<3, 0><<<dim3(2, gridE, RR), blk>>>(
        nullptr, 0, 0, eidx, (long long)2 * EE, x, eattr, (long long)EE * FF,
        p_w + OFF_WK, 69632, HH, bk, HH, p_kb, (long long)EE * HH, HH,
        EE, HH, 272, 0);
    // v
    gemm_tc<3, 0><<<dim3(2, gridE, RR), blk>>>(
        nullptr, 0, 0, eidx, (long long)2 * EE, x, eattr, (long long)EE * FF,
        p_w + OFF_WV, 69632, HH, bv, HH, p_vb, (long long)EE * HH, HH,
        EE, HH, 272, 0);

    // edge softmax (3 passes)
    scores_kernel<<<RR * EE / 8, blk>>>(p_qe, p_kb, eidx, prior, p_sc, p_m);
    ex_kernel<<<RR * EE * NHH / 256, blk>>>(eidx, p_m, p_sc, p_den);
    agg_kernel<<<RR * EE / 8, blk>>>(p_sc, p_den, p_vb, eidx, p_agg);

    // rel_out = gelu(agg @ Wm + bm)
    gemm_tc<0, 1><<<dim3(2, gridN, RR), blk>>>(
        p_agg, (long long)NN * HH, HH, nullptr, 0, nullptr, nullptr, 0,
        p_w + OFF_WM, 65536, HH, bm, HH, p_rel, (long long)NN * HH, HH,
        NN, HH, HH, 0);

    // h = gelu(all_rel @ W_ir1 + b_ir1)   (rel-stacked A loader, K=1536)
    gemm_tc<1, 1><<<dim3(2, gridN, 1), blk>>>(
        p_rel, 0, 0, nullptr, 0, nullptr, nullptr, 0,
        p_w + OFF_WIR1, 0, HH, bir1, 0, p_h1, 0, HH, NN, HH, RR * HH, NN);

    // inter softmax + mix + meta paths
    inter_kernel<<<NN, blk>>>(p_h1, Wir2, bir2, p_rel, p_cat, p_paths);

    // stacked = paths @ Wmp + bmp  (z=3, strided A/C)
    gemm_tc<0, 0><<<dim3(2, gridN, 3), blk>>>(
        p_paths, 256, 768, nullptr, 0, nullptr, nullptr, 0,
        p_w + OFF_WMP, 65536, HH, bmp, HH, p_stk, 256, 768, NN, HH, HH, 0);

    // t = tanh(stacked @ Wa1 + ba1)  viewed as [3N,256] @ [256,128]
    gemm_tc<0, 2><<<dim3(1, grid3N, 1), blk>>>(
        p_stk, 0, HH, nullptr, 0, nullptr, nullptr, 0,
        p_w + OFF_WA1, 0, 128, ba1, 0, p_t, 0, 128, 3 * NN, 128, HH, 0);

    // meta attention + LN -> cat[:,256:]
    meta_kernel<<<NN, blk>>>(p_t, Wa2, p_stk, gmeta, bmeta, p_cat);

    // combined = gelu(cat @ Wc + bc)
    gemm_tc<0, 1><<<dim3(2, gridN, 1), blk>>>(
        p_cat, 0, 2 * HH, nullptr, 0, nullptr, nullptr, 0,
        p_w + OFF_WC, 0, HH, bc, 0, p_comb, 0, HH, NN, HH, 2 * HH, 0);

    // out = LN(x + combined)
    out_kernel<<<NN, blk>>>(x, p_comb, gout, bout, out);
}